// round 1
// baseline (speedup 1.0000x reference)
#include <cuda_runtime.h>
#include <math.h>

#define TPB 256
#define XROW 124   // padded input row (floats): conflict-free float4 LDS

// ---- smem weight layout (float offsets), OUT padded to multiple of 4 ----
#define OW1  0      // 120x60
#define OW2  7200   // 60x32 (30 real)
#define OW3  9120   // 30x12 (10 real)
#define OW4  9480   // 10x4
#define OW5  9520   // 4x12 (10 real)
#define OW6  9568   // 10x32 (30 real)
#define OW7  9888   // 30x60
#define OW8T 11688  // transposed: 120 rows x 60
#define OW9  18888  // 120x12 (10 real)
#define OW10 20328  // 10x12 (10 real)
#define OB1  20448
#define OB2  20508
#define OB3  20540
#define OB4  20552
#define OB5  20556
#define OB6  20568
#define OB7  20600
#define OB8  20660
#define OB9  20780
#define OB10 20792
#define WTOTAL 20804
#define SMEM_FLOATS (TPB*XROW + WTOTAL)
#define SMEM_BYTES  (SMEM_FLOATS*4)

struct Params { const float* w[10]; const float* b[10]; };

__device__ float g_stats[152];   // [0,10) sum_g, [10,50) mu_num, [50,150) cov2 tri
__device__ float g_gmm[212];     // per k (stride 21): mu[4], P[16], const

// ---------- helpers ----------
template<int OUTP>
__device__ __forceinline__ void macc4(float* y, float xi, const float* Wrow) {
#pragma unroll
    for (int j = 0; j < OUTP / 4; j++) {
        float4 w = reinterpret_cast<const float4*>(Wrow)[j];
        y[4*j+0] += xi * w.x;
        y[4*j+1] += xi * w.y;
        y[4*j+2] += xi * w.z;
        y[4*j+3] += xi * w.w;
    }
}

template<int IN, int OUT, int OUTP, bool ACT>
__device__ __forceinline__ void denseR(const float* __restrict__ x, float* __restrict__ y,
                                       const float* __restrict__ W, const float* __restrict__ b) {
#pragma unroll
    for (int j = 0; j < OUTP; j++) y[j] = b[j];
#pragma unroll
    for (int i = 0; i < IN; i++) macc4<OUTP>(y, x[i], W + i * OUTP);
    if (ACT) {
#pragma unroll
        for (int j = 0; j < OUT; j++) y[j] = tanhf(y[j]);
    }
}

template<int IN, int OUT, int OUTP>
__device__ __forceinline__ void loadW(float* dst, const float* __restrict__ src, int tid) {
    const int tot = IN * OUTP;
    for (int idx = tid; idx < tot; idx += TPB) {
        int i = idx / OUTP, j = idx - i * OUTP;
        dst[idx] = (j < OUT) ? src[i * OUT + j] : 0.0f;
    }
}

template<int OUT, int OUTP>
__device__ __forceinline__ void loadB(float* dst, const float* __restrict__ src, int tid) {
    if (tid < OUTP) dst[tid] = (tid < OUT) ? src[tid] : 0.0f;
}

// ---------- phase 1: MLP forward, writes gamma + zc ----------
__global__ __launch_bounds__(TPB, 1)
void phase1(const float* __restrict__ x_in, Params p,
            float* __restrict__ gamma_out, float* __restrict__ zc_out, int N) {
    extern __shared__ float sm[];
    float* sX = sm;
    float* sW = sm + TPB * XROW;
    int tid = threadIdx.x;

    loadW<120,60,60>(sW + OW1,  p.w[0], tid);
    loadW<60,30,32>(sW + OW2,  p.w[1], tid);
    loadW<30,10,12>(sW + OW3,  p.w[2], tid);
    loadW<10,4,4>  (sW + OW4,  p.w[3], tid);
    loadW<4,10,12> (sW + OW5,  p.w[4], tid);
    loadW<10,30,32>(sW + OW6,  p.w[5], tid);
    loadW<30,60,60>(sW + OW7,  p.w[6], tid);
    // w8 transposed: sW8T[d*60+h] = w8[h*120+d]
    for (int idx = tid; idx < 7200; idx += TPB) {
        int d = idx / 60, h = idx - d * 60;
        sW[OW8T + idx] = p.w[7][h * 120 + d];
    }
    loadW<120,10,12>(sW + OW9,  p.w[8], tid);
    loadW<10,10,12> (sW + OW10, p.w[9], tid);
    loadB<60,60>  (sW + OB1,  p.b[0], tid);
    loadB<30,32>  (sW + OB2,  p.b[1], tid);
    loadB<10,12>  (sW + OB3,  p.b[2], tid);
    loadB<4,4>    (sW + OB4,  p.b[3], tid);
    loadB<10,12>  (sW + OB5,  p.b[4], tid);
    loadB<30,32>  (sW + OB6,  p.b[5], tid);
    loadB<60,60>  (sW + OB7,  p.b[6], tid);
    loadB<120,120>(sW + OB8,  p.b[7], tid);
    loadB<10,12>  (sW + OB9,  p.b[8], tid);
    loadB<10,12>  (sW + OB10, p.b[9], tid);

    // stage input tile, coalesced float4
    int base = blockIdx.x * TPB;
    int rows = N - base; if (rows > TPB) rows = TPB;
    const float4* in4 = reinterpret_cast<const float4*>(x_in + (size_t)base * 120);
    for (int idx = tid; idx < rows * 30; idx += TPB) {
        int r = idx / 30, c = idx - 30 * r;
        reinterpret_cast<float4*>(sX + r * XROW)[c] = in4[idx];
    }
    __syncthreads();

    int n = base + tid;
    if (n >= N) return;

    const float* xs = sX + tid * XROW;
    float A[60], B[60];

    // L1: 120->60 tanh (x from smem, float4 chunks)
    {
#pragma unroll
        for (int j = 0; j < 60; j++) A[j] = sW[OB1 + j];
        const float4* xs4 = reinterpret_cast<const float4*>(xs);
        for (int i4 = 0; i4 < 30; i4++) {
            float4 xv = xs4[i4];
            const float* Wr = sW + OW1 + i4 * 4 * 60;
            macc4<60>(A, xv.x, Wr);
            macc4<60>(A, xv.y, Wr + 60);
            macc4<60>(A, xv.z, Wr + 120);
            macc4<60>(A, xv.w, Wr + 180);
        }
#pragma unroll
        for (int j = 0; j < 60; j++) A[j] = tanhf(A[j]);
    }

    denseR<60,30,32,true>(A, B, sW + OW2, sW + OB2);   // L2
    denseR<30,10,12,true>(B, A, sW + OW3, sW + OB3);   // L3
    float zc[4];
    denseR<10,4,4,false>(A, zc, sW + OW4, sW + OB4);   // L4 (latent)
    reinterpret_cast<float4*>(zc_out)[n] = make_float4(zc[0], zc[1], zc[2], zc[3]);

    denseR<4,10,12,true>(zc, B, sW + OW5, sW + OB5);   // L5
    denseR<10,30,32,true>(B, A, sW + OW6, sW + OB6);   // L6
    denseR<30,60,60,true>(A, B, sW + OW7, sW + OB7);   // L7 -> B[60]

    // L8 (60->120, no act) fused with L9 (120->10 tanh)
    float z9[12];
#pragma unroll
    for (int j = 0; j < 12; j++) z9[j] = sW[OB9 + j];
    for (int d = 0; d < 120; d++) {
        float acc = sW[OB8 + d];
        const float* Wr = sW + OW8T + d * 60;
#pragma unroll
        for (int h4 = 0; h4 < 15; h4++) {
            float4 w = reinterpret_cast<const float4*>(Wr)[h4];
            acc += B[4*h4+0] * w.x + B[4*h4+1] * w.y + B[4*h4+2] * w.z + B[4*h4+3] * w.w;
        }
        macc4<12>(z9, acc, sW + OW9 + d * 12);
    }
#pragma unroll
    for (int j = 0; j < 10; j++) z9[j] = tanhf(z9[j]);

    // L10 + softmax
    float g[12];
    denseR<10,10,12,false>(z9, g, sW + OW10, sW + OB10);
    float m = g[0];
#pragma unroll
    for (int j = 1; j < 10; j++) m = fmaxf(m, g[j]);
    float s = 0.f;
#pragma unroll
    for (int j = 0; j < 10; j++) { g[j] = expf(g[j] - m); s += g[j]; }
    float inv = 1.0f / s;
    float2* gp = reinterpret_cast<float2*>(gamma_out + (size_t)n * 10);
#pragma unroll
    for (int t = 0; t < 5; t++) gp[t] = make_float2(g[2*t] * inv, g[2*t+1] * inv);
}

// ---------- zero stats ----------
__global__ void zero_stats() {
    int t = threadIdx.x;
    if (t < 152) g_stats[t] = 0.0f;
}

// ---------- phase 2: moment reduction ----------
__global__ __launch_bounds__(256)
void phase2(const float* __restrict__ gamma, const float* __restrict__ zc, int N) {
    float acc[150];
#pragma unroll
    for (int v = 0; v < 150; v++) acc[v] = 0.0f;

    int stride = gridDim.x * blockDim.x;
    for (int n = blockIdx.x * blockDim.x + threadIdx.x; n < N; n += stride) {
        float g[10];
        const float2* gp = reinterpret_cast<const float2*>(gamma + (size_t)n * 10);
#pragma unroll
        for (int t = 0; t < 5; t++) { float2 v = gp[t]; g[2*t] = v.x; g[2*t+1] = v.y; }
        float4 z4 = reinterpret_cast<const float4*>(zc)[n];
        float zv[4] = {z4.x, z4.y, z4.z, z4.w};
        float zz[10];
        {
            int t = 0;
#pragma unroll
            for (int d = 0; d < 4; d++)
#pragma unroll
                for (int e = d; e < 4; e++) zz[t++] = zv[d] * zv[e];
        }
#pragma unroll
        for (int k = 0; k < 10; k++) {
            float gk = g[k];
            acc[k] += gk;
#pragma unroll
            for (int d = 0; d < 4; d++) acc[10 + k*4 + d] += gk * zv[d];
#pragma unroll
            for (int t = 0; t < 10; t++) acc[50 + k*10 + t] += gk * zz[t];
        }
    }
    // warp tree reduce
#pragma unroll
    for (int v = 0; v < 150; v++) {
        float x = acc[v];
        x += __shfl_xor_sync(0xffffffffu, x, 16);
        x += __shfl_xor_sync(0xffffffffu, x, 8);
        x += __shfl_xor_sync(0xffffffffu, x, 4);
        x += __shfl_xor_sync(0xffffffffu, x, 2);
        x += __shfl_xor_sync(0xffffffffu, x, 1);
        acc[v] = x;
    }
    if ((threadIdx.x & 31) == 0) {
#pragma unroll
        for (int v = 0; v < 150; v++) atomicAdd(&g_stats[v], acc[v]);
    }
}

// ---------- phase 3: GMM params, Cholesky, precision ----------
__global__ void phase3(float* __restrict__ cov_out, float invN) {
    int k = threadIdx.x;
    if (k >= 10) return;
    float sg = g_stats[k];
    float isg = 1.0f / sg;
    float mu[4];
#pragma unroll
    for (int d = 0; d < 4; d++) mu[d] = g_stats[10 + 4*k + d] * isg;
    float C[4][4];
    {
        int t = 0;
#pragma unroll
        for (int d = 0; d < 4; d++)
#pragma unroll
            for (int e = d; e < 4; e++) {
                float c = g_stats[50 + 10*k + t] * isg - mu[d] * mu[e];
                C[d][e] = c; C[e][d] = c; t++;
            }
    }
#pragma unroll
    for (int d = 0; d < 4; d++)
#pragma unroll
        for (int e = 0; e < 4; e++) cov_out[k*16 + d*4 + e] = C[d][e];

#pragma unroll
    for (int d = 0; d < 4; d++) C[d][d] += 1e-6f;

    float L00 = sqrtf(C[0][0]);
    float L10 = C[1][0] / L00, L20 = C[2][0] / L00, L30 = C[3][0] / L00;
    float L11 = sqrtf(C[1][1] - L10*L10);
    float L21 = (C[2][1] - L20*L10) / L11;
    float L31 = (C[3][1] - L30*L10) / L11;
    float L22 = sqrtf(C[2][2] - L20*L20 - L21*L21);
    float L32 = (C[3][2] - L30*L20 - L31*L21) / L22;
    float L33 = sqrtf(C[3][3] - L30*L30 - L31*L31 - L32*L32);
    float logdet = 2.0f * (logf(L00) + logf(L11) + logf(L22) + logf(L33));

    float M00 = 1.0f/L00, M11 = 1.0f/L11, M22 = 1.0f/L22, M33 = 1.0f/L33;
    float M10 = -L10 * M00 * M11;
    float M20 = -(L20*M00 + L21*M10) * M22;
    float M21 = -L21 * M11 * M22;
    float M30 = -(L30*M00 + L31*M10 + L32*M20) * M33;
    float M31 = -(L31*M11 + L32*M21) * M33;
    float M32 = -L32 * M22 * M33;

    float P[4][4];
    P[0][0] = M00*M00 + M10*M10 + M20*M20 + M30*M30;
    P[0][1] = M10*M11 + M20*M21 + M30*M31;
    P[0][2] = M20*M22 + M30*M32;
    P[0][3] = M30*M33;
    P[1][1] = M11*M11 + M21*M21 + M31*M31;
    P[1][2] = M21*M22 + M31*M32;
    P[1][3] = M31*M33;
    P[2][2] = M22*M22 + M32*M32;
    P[2][3] = M32*M33;
    P[3][3] = M33*M33;
    P[1][0] = P[0][1]; P[2][0] = P[0][2]; P[3][0] = P[0][3];
    P[2][1] = P[1][2]; P[3][1] = P[1][3]; P[3][2] = P[2][3];

    float phi = sg * invN;
    const float LOG2PI = 1.8378770664093453f;
    float ck = logf(phi) - 0.5f * (logdet + 4.0f * LOG2PI);

    float* o = g_gmm + k * 21;
#pragma unroll
    for (int d = 0; d < 4; d++) o[d] = mu[d];
#pragma unroll
    for (int d = 0; d < 4; d++)
#pragma unroll
        for (int e = 0; e < 4; e++) o[4 + d*4 + e] = P[d][e];
    o[20] = ck;
}

// ---------- phase 4: per-sample energy ----------
__global__ __launch_bounds__(256)
void phase4(const float* __restrict__ zc, float* __restrict__ energy, int N) {
    __shared__ float sp[212];
    if (threadIdx.x < 212) sp[threadIdx.x] = g_gmm[threadIdx.x];
    __syncthreads();
    int n = blockIdx.x * blockDim.x + threadIdx.x;
    if (n >= N) return;
    float4 z = reinterpret_cast<const float4*>(zc)[n];
    float lp[10];
    float m = -1e30f;
#pragma unroll
    for (int k = 0; k < 10; k++) {
        const float* o = sp + k * 21;
        float d0 = z.x - o[0], d1 = z.y - o[1], d2 = z.z - o[2], d3 = z.w - o[3];
        const float* P = o + 4;
        float q = d0 * (P[0]*d0  + P[1]*d1  + P[2]*d2  + P[3]*d3)
                + d1 * (P[4]*d0  + P[5]*d1  + P[6]*d2  + P[7]*d3)
                + d2 * (P[8]*d0  + P[9]*d1  + P[10]*d2 + P[11]*d3)
                + d3 * (P[12]*d0 + P[13]*d1 + P[14]*d2 + P[15]*d3);
        lp[k] = o[20] - 0.5f * q;
        m = fmaxf(m, lp[k]);
    }
    float s = 0.f;
#pragma unroll
    for (int k = 0; k < 10; k++) s += expf(lp[k] - m);
    energy[n] = -(m + logf(s));
}

// ---------- launcher ----------
extern "C" void kernel_launch(void* const* d_in, const int* in_sizes, int n_in,
                              void* d_out, int out_size) {
    const float* x = (const float*)d_in[0];
    Params p;
    for (int i = 0; i < 10; i++) {
        p.w[i] = (const float*)d_in[1 + 2*i];
        p.b[i] = (const float*)d_in[2 + 2*i];
    }
    int N = in_sizes[0] / 120;

    float* out    = (float*)d_out;
    float* energy = out;                       // [N]
    float* gamma  = out + N;                   // [N,10]
    float* zcbuf  = out + (size_t)11 * N;      // [N,4]
    float* covbuf = out + (size_t)15 * N;      // [10,4,4]

    cudaFuncSetAttribute(phase1, cudaFuncAttributeMaxDynamicSharedMemorySize, SMEM_BYTES);

    zero_stats<<<1, 160>>>();
    phase1<<<(N + TPB - 1) / TPB, TPB, SMEM_BYTES>>>(x, p, gamma, zcbuf, N);
    phase2<<<296, 256>>>(gamma, zcbuf, N);
    phase3<<<1, 32>>>(covbuf, 1.0f / (float)N);
    phase4<<<(N + 255) / 256, 256>>>(zcbuf, energy, N);
}

// round 2
// speedup vs baseline: 1.3941x; 1.3941x over previous
#include <cuda_runtime.h>
#include <math.h>

typedef unsigned long long ull;

#define TPB 256
#define XROW 124   // padded input row (floats)

// ---- smem weight layout (float offsets); all OUT padded to %4==0, offsets %4==0 ----
#define OW1  0      // 120x60
#define OW2  7200   // 60x32 (30 real)
#define OW3  9120   // 30x12 (10 real)
#define OW4  9480   // 10x4
#define OW5  9520   // 4x12 (10 real)
#define OW6  9568   // 10x32 (30 real)
#define OW7  9888   // 30x60
#define OW89 11688  // fused (W8@W9): 60x12 (10 real)
#define OW10 12408  // 10x12 (10 real)
#define OB1  12528
#define OB2  12588
#define OB3  12620
#define OB4  12632
#define OB5  12636
#define OB6  12648
#define OB7  12680
#define OB89 12740
#define OB10 12752
#define WTOTAL 12764
#define SMEM_FLOATS (TPB*XROW + WTOTAL)
#define SMEM_BYTES  (SMEM_FLOATS*4)

struct Params { const float* w[10]; const float* b[10]; };

__device__ float g_stats[152];   // [0,10) sum_g, [10,50) mu_num, [50,150) cov 2nd-moment tri
__device__ float g_gmm[212];     // per k (stride 21): mu[4], P[16], logconst
__device__ float g_w89[732];     // fused W89 [60x12] + b89 [12]

// ---------- packed f32x2 helpers ----------
__device__ __forceinline__ ull fma2(ull a, ull b, ull c) {
    ull d; asm("fma.rn.f32x2 %0, %1, %2, %3;" : "=l"(d) : "l"(a), "l"(b), "l"(c)); return d;
}
__device__ __forceinline__ ull pack2(float x) {
    ull r; asm("mov.b64 %0, {%1, %1};" : "=l"(r) : "f"(x)); return r;
}
__device__ __forceinline__ void unpack2(float& lo, float& hi, ull v) {
    asm("mov.b64 {%0, %1}, %2;" : "=f"(lo), "=f"(hi) : "l"(v));
}
__device__ __forceinline__ float tanh_fast(float x) {
    float xc = fminf(fmaxf(x, -10.0f), 10.0f);
    float e = __expf(2.0f * xc);
    return __fdividef(e - 1.0f, e + 1.0f);
}

// ---------- dense layer on packed accumulators ----------
template<int IN, int OUT, int OUTP, bool ACT>
__device__ __forceinline__ void dense2(const float* __restrict__ x, float* __restrict__ y,
                                       const float* __restrict__ W, const float* __restrict__ b) {
    constexpr int P = OUTP / 2;
    ull acc[P];
#pragma unroll
    for (int j = 0; j < P; j++) acc[j] = reinterpret_cast<const ull*>(b)[j];
#pragma unroll 2
    for (int i = 0; i < IN; i++) {
        ull xp = pack2(x[i]);
        const ulonglong2* Wr = reinterpret_cast<const ulonglong2*>(W + i * OUTP);
#pragma unroll
        for (int j = 0; j < P / 2; j++) {
            ulonglong2 w = Wr[j];
            acc[2*j]   = fma2(xp, w.x, acc[2*j]);
            acc[2*j+1] = fma2(xp, w.y, acc[2*j+1]);
        }
    }
#pragma unroll
    for (int j = 0; j < P; j++) { float lo, hi; unpack2(lo, hi, acc[j]); y[2*j] = lo; y[2*j+1] = hi; }
    if (ACT) {
#pragma unroll
        for (int j = 0; j < OUT; j++) y[j] = tanh_fast(y[j]);
    }
}

// ---------- smem loaders ----------
template<int IN, int OUT, int OUTP>
__device__ __forceinline__ void loadW(float* dst, const float* __restrict__ src, int tid) {
    const int tot = IN * OUTP;
    for (int idx = tid; idx < tot; idx += TPB) {
        int i = idx / OUTP, j = idx - i * OUTP;
        dst[idx] = (j < OUT) ? src[i * OUT + j] : 0.0f;
    }
}
template<int OUT, int OUTP>
__device__ __forceinline__ void loadB(float* dst, const float* __restrict__ src, int tid) {
    if (tid < OUTP) dst[tid] = (tid < OUT) ? src[tid] : 0.0f;
}

// ---------- prep: zero stats + build fused W89 = W8@W9, b89 = b8@W9 + b9 ----------
__global__ void prep(const float* __restrict__ w8, const float* __restrict__ b8,
                     const float* __restrict__ w9, const float* __restrict__ b9) {
    int t = threadIdx.x;
    if (t < 152) g_stats[t] = 0.0f;
    if (t < 720) {
        int a = t / 12, j = t - a * 12;
        float s = 0.0f;
        if (j < 10) {
            for (int d = 0; d < 120; d++) s += w8[a * 120 + d] * w9[d * 10 + j];
        }
        g_w89[t] = s;
    }
    if (t >= 720 && t < 732) {
        int j = t - 720;
        float s = 0.0f;
        if (j < 10) {
            for (int d = 0; d < 120; d++) s += b8[d] * w9[d * 10 + j];
            s += b9[j];
        }
        g_w89[t] = s;
    }
}

// ---------- phase 1: MLP forward (L8/L9 fused), writes gamma + zc ----------
__global__ __launch_bounds__(TPB, 1)
void phase1(const float* __restrict__ x_in, Params p,
            float* __restrict__ gamma_out, float* __restrict__ zc_out, int N) {
    extern __shared__ float sm[];
    float* sX = sm;
    float* sW = sm + TPB * XROW;
    int tid = threadIdx.x;

    loadW<120,60,60>(sW + OW1,  p.w[0], tid);
    loadW<60,30,32> (sW + OW2,  p.w[1], tid);
    loadW<30,10,12> (sW + OW3,  p.w[2], tid);
    loadW<10,4,4>   (sW + OW4,  p.w[3], tid);
    loadW<4,10,12>  (sW + OW5,  p.w[4], tid);
    loadW<10,30,32> (sW + OW6,  p.w[5], tid);
    loadW<30,60,60> (sW + OW7,  p.w[6], tid);
    for (int idx = tid; idx < 732; idx += TPB) {
        float v = g_w89[idx];
        if (idx < 720) sW[OW89 + idx] = v; else sW[OB89 + idx - 720] = v;
    }
    loadW<10,10,12> (sW + OW10, p.w[9], tid);
    loadB<60,60>  (sW + OB1,  p.b[0], tid);
    loadB<30,32>  (sW + OB2,  p.b[1], tid);
    loadB<10,12>  (sW + OB3,  p.b[2], tid);
    loadB<4,4>    (sW + OB4,  p.b[3], tid);
    loadB<10,12>  (sW + OB5,  p.b[4], tid);
    loadB<30,32>  (sW + OB6,  p.b[5], tid);
    loadB<60,60>  (sW + OB7,  p.b[6], tid);
    loadB<10,12>  (sW + OB10, p.b[9], tid);

    // stage input tile (coalesced float4)
    int base = blockIdx.x * TPB;
    int rows = N - base; if (rows > TPB) rows = TPB;
    const float4* in4 = reinterpret_cast<const float4*>(x_in + (size_t)base * 120);
    for (int idx = tid; idx < rows * 30; idx += TPB) {
        int r = idx / 30, c = idx - 30 * r;
        reinterpret_cast<float4*>(sX + r * XROW)[c] = in4[idx];
    }
    __syncthreads();

    int n = base + tid;
    if (n >= N) return;

    const float4* xs4 = reinterpret_cast<const float4*>(sX + tid * XROW);
    float A[60], B[60];

    // L1: 120->60 tanh, x from smem in float4 chunks, packed accumulators
    {
        ull acc[30];
#pragma unroll
        for (int j = 0; j < 30; j++) acc[j] = reinterpret_cast<const ull*>(sW + OB1)[j];
#pragma unroll 2
        for (int i4 = 0; i4 < 30; i4++) {
            float4 xv = xs4[i4];
            float xr[4] = {xv.x, xv.y, xv.z, xv.w};
#pragma unroll
            for (int s = 0; s < 4; s++) {
                ull xp = pack2(xr[s]);
                const ulonglong2* Wr = reinterpret_cast<const ulonglong2*>(sW + OW1 + (i4 * 4 + s) * 60);
#pragma unroll
                for (int j = 0; j < 15; j++) {
                    ulonglong2 w = Wr[j];
                    acc[2*j]   = fma2(xp, w.x, acc[2*j]);
                    acc[2*j+1] = fma2(xp, w.y, acc[2*j+1]);
                }
            }
        }
#pragma unroll
        for (int j = 0; j < 30; j++) { float lo, hi; unpack2(lo, hi, acc[j]); A[2*j] = lo; A[2*j+1] = hi; }
#pragma unroll
        for (int j = 0; j < 60; j++) A[j] = tanh_fast(A[j]);
    }

    dense2<60,30,32,true>(A, B, sW + OW2, sW + OB2);   // L2
    dense2<30,10,12,true>(B, A, sW + OW3, sW + OB3);   // L3
    float zc[4];
    dense2<10,4,4,false>(A, zc, sW + OW4, sW + OB4);   // L4 (latent)
    reinterpret_cast<float4*>(zc_out)[n] = make_float4(zc[0], zc[1], zc[2], zc[3]);

    dense2<4,10,12,true>(zc, B, sW + OW5, sW + OB5);   // L5
    dense2<10,30,32,true>(B, A, sW + OW6, sW + OB6);   // L6
    dense2<30,60,60,true>(A, B, sW + OW7, sW + OB7);   // L7
    float z9[12];
    dense2<60,10,12,true>(B, z9, sW + OW89, sW + OB89); // fused L8+L9 (tanh)

    // L10 + softmax
    float g[12];
    dense2<10,10,12,false>(z9, g, sW + OW10, sW + OB10);
    float m = g[0];
#pragma unroll
    for (int j = 1; j < 10; j++) m = fmaxf(m, g[j]);
    float s = 0.f;
#pragma unroll
    for (int j = 0; j < 10; j++) { g[j] = __expf(g[j] - m); s += g[j]; }
    float inv = __fdividef(1.0f, s);
    float2* gp = reinterpret_cast<float2*>(gamma_out + (size_t)n * 10);
#pragma unroll
    for (int t = 0; t < 5; t++) gp[t] = make_float2(g[2*t] * inv, g[2*t+1] * inv);
}

// ---------- phase 2: moment reduction ----------
__global__ __launch_bounds__(256)
void phase2(const float* __restrict__ gamma, const float* __restrict__ zc, int N) {
    float acc[150];
#pragma unroll
    for (int v = 0; v < 150; v++) acc[v] = 0.0f;

    int stride = gridDim.x * blockDim.x;
    for (int n = blockIdx.x * blockDim.x + threadIdx.x; n < N; n += stride) {
        float g[10];
        const float2* gp = reinterpret_cast<const float2*>(gamma + (size_t)n * 10);
#pragma unroll
        for (int t = 0; t < 5; t++) { float2 v = gp[t]; g[2*t] = v.x; g[2*t+1] = v.y; }
        float4 z4 = reinterpret_cast<const float4*>(zc)[n];
        float zv[4] = {z4.x, z4.y, z4.z, z4.w};
        float zz[10];
        {
            int t = 0;
#pragma unroll
            for (int d = 0; d < 4; d++)
#pragma unroll
                for (int e = d; e < 4; e++) zz[t++] = zv[d] * zv[e];
        }
#pragma unroll
        for (int k = 0; k < 10; k++) {
            float gk = g[k];
            acc[k] += gk;
#pragma unroll
            for (int d = 0; d < 4; d++) acc[10 + k*4 + d] += gk * zv[d];
#pragma unroll
            for (int t = 0; t < 10; t++) acc[50 + k*10 + t] += gk * zz[t];
        }
    }
#pragma unroll
    for (int v = 0; v < 150; v++) {
        float x = acc[v];
        x += __shfl_xor_sync(0xffffffffu, x, 16);
        x += __shfl_xor_sync(0xffffffffu, x, 8);
        x += __shfl_xor_sync(0xffffffffu, x, 4);
        x += __shfl_xor_sync(0xffffffffu, x, 2);
        x += __shfl_xor_sync(0xffffffffu, x, 1);
        acc[v] = x;
    }
    if ((threadIdx.x & 31) == 0) {
#pragma unroll
        for (int v = 0; v < 150; v++) atomicAdd(&g_stats[v], acc[v]);
    }
}

// ---------- phase 3: GMM params, Cholesky, precision ----------
__global__ void phase3(float* __restrict__ cov_out, float invN) {
    int k = threadIdx.x;
    if (k >= 10) return;
    float sg = g_stats[k];
    float isg = 1.0f / sg;
    float mu[4];
#pragma unroll
    for (int d = 0; d < 4; d++) mu[d] = g_stats[10 + 4*k + d] * isg;
    float C[4][4];
    {
        int t = 0;
#pragma unroll
        for (int d = 0; d < 4; d++)
#pragma unroll
            for (int e = d; e < 4; e++) {
                float c = g_stats[50 + 10*k + t] * isg - mu[d] * mu[e];
                C[d][e] = c; C[e][d] = c; t++;
            }
    }
#pragma unroll
    for (int d = 0; d < 4; d++)
#pragma unroll
        for (int e = 0; e < 4; e++) cov_out[k*16 + d*4 + e] = C[d][e];

#pragma unroll
    for (int d = 0; d < 4; d++) C[d][d] += 1e-6f;

    float L00 = sqrtf(C[0][0]);
    float L10 = C[1][0] / L00, L20 = C[2][0] / L00, L30 = C[3][0] / L00;
    float L11 = sqrtf(C[1][1] - L10*L10);
    float L21 = (C[2][1] - L20*L10) / L11;
    float L31 = (C[3][1] - L30*L10) / L11;
    float L22 = sqrtf(C[2][2] - L20*L20 - L21*L21);
    float L32 = (C[3][2] - L30*L20 - L31*L21) / L22;
    float L33 = sqrtf(C[3][3] - L30*L30 - L31*L31 - L32*L32);
    float logdet = 2.0f * (logf(L00) + logf(L11) + logf(L22) + logf(L33));

    float M00 = 1.0f/L00, M11 = 1.0f/L11, M22 = 1.0f/L22, M33 = 1.0f/L33;
    float M10 = -L10 * M00 * M11;
    float M20 = -(L20*M00 + L21*M10) * M22;
    float M21 = -L21 * M11 * M22;
    float M30 = -(L30*M00 + L31*M10 + L32*M20) * M33;
    float M31 = -(L31*M11 + L32*M21) * M33;
    float M32 = -L32 * M22 * M33;

    float P[4][4];
    P[0][0] = M00*M00 + M10*M10 + M20*M20 + M30*M30;
    P[0][1] = M10*M11 + M20*M21 + M30*M31;
    P[0][2] = M20*M22 + M30*M32;
    P[0][3] = M30*M33;
    P[1][1] = M11*M11 + M21*M21 + M31*M31;
    P[1][2] = M21*M22 + M31*M32;
    P[1][3] = M31*M33;
    P[2][2] = M22*M22 + M32*M32;
    P[2][3] = M32*M33;
    P[3][3] = M33*M33;
    P[1][0] = P[0][1]; P[2][0] = P[0][2]; P[3][0] = P[0][3];
    P[2][1] = P[1][2]; P[3][1] = P[1][3]; P[3][2] = P[2][3];

    float phi = sg * invN;
    const float LOG2PI = 1.8378770664093453f;
    float ck = logf(phi) - 0.5f * (logdet + 4.0f * LOG2PI);

    float* o = g_gmm + k * 21;
#pragma unroll
    for (int d = 0; d < 4; d++) o[d] = mu[d];
#pragma unroll
    for (int d = 0; d < 4; d++)
#pragma unroll
        for (int e = 0; e < 4; e++) o[4 + d*4 + e] = P[d][e];
    o[20] = ck;
}

// ---------- phase 4: per-sample energy ----------
__global__ __launch_bounds__(256)
void phase4(const float* __restrict__ zc, float* __restrict__ energy, int N) {
    __shared__ float sp[212];
    if (threadIdx.x < 212) sp[threadIdx.x] = g_gmm[threadIdx.x];
    __syncthreads();
    int n = blockIdx.x * blockDim.x + threadIdx.x;
    if (n >= N) return;
    float4 z = reinterpret_cast<const float4*>(zc)[n];
    float lp[10];
    float m = -1e30f;
#pragma unroll
    for (int k = 0; k < 10; k++) {
        const float* o = sp + k * 21;
        float d0 = z.x - o[0], d1 = z.y - o[1], d2 = z.z - o[2], d3 = z.w - o[3];
        const float* P = o + 4;
        float q = d0 * (P[0]*d0  + P[1]*d1  + P[2]*d2  + P[3]*d3)
                + d1 * (P[4]*d0  + P[5]*d1  + P[6]*d2  + P[7]*d3)
                + d2 * (P[8]*d0  + P[9]*d1  + P[10]*d2 + P[11]*d3)
                + d3 * (P[12]*d0 + P[13]*d1 + P[14]*d2 + P[15]*d3);
        lp[k] = o[20] - 0.5f * q;
        m = fmaxf(m, lp[k]);
    }
    float s = 0.f;
#pragma unroll
    for (int k = 0; k < 10; k++) s += __expf(lp[k] - m);
    energy[n] = -(m + __logf(s));
}

// ---------- launcher ----------
extern "C" void kernel_launch(void* const* d_in, const int* in_sizes, int n_in,
                              void* d_out, int out_size) {
    const float* x = (const float*)d_in[0];
    Params p;
    for (int i = 0; i < 10; i++) {
        p.w[i] = (const float*)d_in[1 + 2*i];
        p.b[i] = (const float*)d_in[2 + 2*i];
    }
    int N = in_sizes[0] / 120;

    float* out    = (float*)d_out;
    float* energy = out;                       // [N]
    float* gamma  = out + N;                   // [N,10]
    float* zcbuf  = out + (size_t)11 * N;      // [N,4]
    float* covbuf = out + (size_t)15 * N;      // [10,4,4]

    cudaFuncSetAttribute(phase1, cudaFuncAttributeMaxDynamicSharedMemorySize, SMEM_BYTES);

    prep<<<1, 768>>>(p.w[7], p.b[7], p.w[8], p.b[8]);
    phase1<<<(N + TPB - 1) / TPB, TPB, SMEM_BYTES>>>(x, p, gamma, zcbuf, N);
    phase2<<<296, 256>>>(gamma, zcbuf, N);
    phase3<<<1, 32>>>(covbuf, 1.0f / (float)N);
    phase4<<<(N + 255) / 256, 256>>>(zcbuf, energy, N);
}

// round 3
// speedup vs baseline: 1.4995x; 1.0756x over previous
#include <cuda_runtime.h>
#include <math.h>

typedef unsigned long long ull;

#define TPB 256
#define XROW 60    // half input row staged per pass (conflict-free float4 LDS)

// ---- smem weight layout (float offsets); OUT padded to %4==0 ----
#define OW1  0      // 120x60
#define OW2  7200   // 60x32 (30 real)
#define OW3  9120   // 30x12 (10 real)
#define OW4  9480   // 10x4
#define OW5  9520   // 4x12 (10 real)
#define OW6  9568   // 10x32 (30 real)
#define OW7  9888   // 30x60
#define OW89 11688  // fused (W8@W9): 60x12 (10 real)
#define OW10 12408  // 10x12 (10 real)
#define OB1  12528
#define OB2  12588
#define OB3  12620
#define OB4  12632
#define OB5  12636
#define OB6  12648
#define OB7  12680
#define OB89 12740
#define OB10 12752
#define WTOTAL 12764                 // divisible by 4
#define SMEM_FLOATS (TPB*XROW + WTOTAL)
#define SMEM_BYTES  (SMEM_FLOATS*4)  // 112,496 B -> 2 CTAs/SM

struct Params { const float* w[10]; const float* b[10]; };

__device__ float g_stats[152];   // [0,10) sum_g, [10,50) mu_num, [50,150) 2nd-moment tri
__device__ float g_gmm[212];     // per k (stride 21): mu[4], P[16], logconst
__device__ float g_wpad[WTOTAL]; // padded + fused weight image

// ---------- packed f32x2 helpers ----------
__device__ __forceinline__ ull fma2(ull a, ull b, ull c) {
    ull d; asm("fma.rn.f32x2 %0, %1, %2, %3;" : "=l"(d) : "l"(a), "l"(b), "l"(c)); return d;
}
__device__ __forceinline__ ull pack2(float x) {
    ull r; asm("mov.b64 %0, {%1, %1};" : "=l"(r) : "f"(x)); return r;
}
__device__ __forceinline__ void unpack2(float& lo, float& hi, ull v) {
    asm("mov.b64 {%0, %1}, %2;" : "=f"(lo), "=f"(hi) : "l"(v));
}
__device__ __forceinline__ float tanh_fast(float x) {
    float xc = fminf(fmaxf(x, -10.0f), 10.0f);
    float e = __expf(2.0f * xc);
    return __fdividef(e - 1.0f, e + 1.0f);
}

// ---------- dense layer on packed accumulators ----------
template<int IN, int OUT, int OUTP, bool ACT>
__device__ __forceinline__ void dense2(const float* __restrict__ x, float* __restrict__ y,
                                       const float* __restrict__ W, const float* __restrict__ b) {
    constexpr int P = OUTP / 2;
    ull acc[P];
#pragma unroll
    for (int j = 0; j < P; j++) acc[j] = reinterpret_cast<const ull*>(b)[j];
#pragma unroll 2
    for (int i = 0; i < IN; i++) {
        ull xp = pack2(x[i]);
        const ulonglong2* Wr = reinterpret_cast<const ulonglong2*>(W + i * OUTP);
#pragma unroll
        for (int j = 0; j < P / 2; j++) {
            ulonglong2 w = Wr[j];
            acc[2*j]   = fma2(xp, w.x, acc[2*j]);
            acc[2*j+1] = fma2(xp, w.y, acc[2*j+1]);
        }
    }
#pragma unroll
    for (int j = 0; j < P; j++) { float lo, hi; unpack2(lo, hi, acc[j]); y[2*j] = lo; y[2*j+1] = hi; }
    if (ACT) {
#pragma unroll
        for (int j = 0; j < OUT; j++) y[j] = tanh_fast(y[j]);
    }
}

// ---------- prep: zero stats + build padded/fused weight image ----------
__device__ __forceinline__ void padcpy(int off, const float* __restrict__ src,
                                       int IN, int OUT, int OUTP, int tid, int nth) {
    for (int idx = tid; idx < IN * OUTP; idx += nth) {
        int i = idx / OUTP, j = idx - i * OUTP;
        g_wpad[off + idx] = (j < OUT) ? src[i * OUT + j] : 0.0f;
    }
}
__device__ __forceinline__ void padb(int off, const float* __restrict__ src,
                                     int OUT, int OUTP, int tid) {
    if (tid < OUTP) g_wpad[off + tid] = (tid < OUT) ? src[tid] : 0.0f;
}

__global__ void prep(Params p) {
    int tid = threadIdx.x, nth = blockDim.x;
    if (tid < 152) g_stats[tid] = 0.0f;
    padcpy(OW1,  p.w[0], 120, 60, 60, tid, nth);
    padcpy(OW2,  p.w[1],  60, 30, 32, tid, nth);
    padcpy(OW3,  p.w[2],  30, 10, 12, tid, nth);
    padcpy(OW4,  p.w[3],  10,  4,  4, tid, nth);
    padcpy(OW5,  p.w[4],   4, 10, 12, tid, nth);
    padcpy(OW6,  p.w[5],  10, 30, 32, tid, nth);
    padcpy(OW7,  p.w[6],  30, 60, 60, tid, nth);
    padcpy(OW10, p.w[9],  10, 10, 12, tid, nth);
    // fused W89 = W8 @ W9 [60x10 -> 60x12], b89 = b8 @ W9 + b9
    for (int idx = tid; idx < 720; idx += nth) {
        int a = idx / 12, j = idx - a * 12;
        float s = 0.0f;
        if (j < 10)
            for (int d = 0; d < 120; d++) s += p.w[7][a * 120 + d] * p.w[8][d * 10 + j];
        g_wpad[OW89 + idx] = s;
    }
    if (tid < 12) {
        int j = tid;
        float s = 0.0f;
        if (j < 10) {
            for (int d = 0; d < 120; d++) s += p.b[7][d] * p.w[8][d * 10 + j];
            s += p.b[8][j];
        }
        g_wpad[OB89 + j] = s;
    }
    padb(OB1,  p.b[0], 60, 60, tid);
    padb(OB2,  p.b[1], 30, 32, tid);
    padb(OB3,  p.b[2], 10, 12, tid);
    padb(OB4,  p.b[3],  4,  4, tid);
    padb(OB5,  p.b[4], 10, 12, tid);
    padb(OB6,  p.b[5], 30, 32, tid);
    padb(OB7,  p.b[6], 60, 60, tid);
    padb(OB10, p.b[9], 10, 12, tid);
}

// ---------- phase 1: MLP forward (two-pass L1 staging), writes gamma + zc ----------
__global__ __launch_bounds__(TPB, 2)
void phase1(const float* __restrict__ x_in,
            float* __restrict__ gamma_out, float* __restrict__ zc_out, int N) {
    extern __shared__ float sm[];
    float* sX = sm;                       // TPB x 60 floats
    float* sW = sm + TPB * XROW;
    int tid = threadIdx.x;

    // weight prologue: clean float4 copy of the padded image
    {
        const float4* src = reinterpret_cast<const float4*>(g_wpad);
        float4* dst = reinterpret_cast<float4*>(sW);
        for (int idx = tid; idx < WTOTAL / 4; idx += TPB) dst[idx] = src[idx];
    }

    int base = blockIdx.x * TPB;
    int rows = N - base; if (rows > TPB) rows = TPB;
    const float4* in4 = reinterpret_cast<const float4*>(x_in + (size_t)base * 120);

    // stage first half (cols 0..59)
    for (int idx = tid; idx < rows * 15; idx += TPB) {
        int r = idx / 15, c = idx - 15 * r;
        reinterpret_cast<float4*>(sX + r * XROW)[c] = in4[r * 30 + c];
    }
    __syncthreads();

    int n = base + tid;
    bool active = (n < N);
    const float4* xs4 = reinterpret_cast<const float4*>(sX + tid * XROW);

    ull acc1[30];
    if (active) {
#pragma unroll
        for (int j = 0; j < 30; j++) acc1[j] = reinterpret_cast<const ull*>(sW + OB1)[j];
#pragma unroll 2
        for (int i4 = 0; i4 < 15; i4++) {
            float4 xv = xs4[i4];
            float xr[4] = {xv.x, xv.y, xv.z, xv.w};
#pragma unroll
            for (int s = 0; s < 4; s++) {
                ull xp = pack2(xr[s]);
                const ulonglong2* Wr = reinterpret_cast<const ulonglong2*>(sW + OW1 + (i4 * 4 + s) * 60);
#pragma unroll
                for (int j = 0; j < 15; j++) {
                    ulonglong2 w = Wr[j];
                    acc1[2*j]   = fma2(xp, w.x, acc1[2*j]);
                    acc1[2*j+1] = fma2(xp, w.y, acc1[2*j+1]);
                }
            }
        }
    }
    __syncthreads();
    // stage second half (cols 60..119)
    for (int idx = tid; idx < rows * 15; idx += TPB) {
        int r = idx / 15, c = idx - 15 * r;
        reinterpret_cast<float4*>(sX + r * XROW)[c] = in4[r * 30 + 15 + c];
    }
    __syncthreads();

    if (!active) return;

    float A[60], B[60];
    {
#pragma unroll 2
        for (int i4 = 0; i4 < 15; i4++) {
            float4 xv = xs4[i4];
            float xr[4] = {xv.x, xv.y, xv.z, xv.w};
#pragma unroll
            for (int s = 0; s < 4; s++) {
                ull xp = pack2(xr[s]);
                const ulonglong2* Wr = reinterpret_cast<const ulonglong2*>(sW + OW1 + (60 + i4 * 4 + s) * 60);
#pragma unroll
                for (int j = 0; j < 15; j++) {
                    ulonglong2 w = Wr[j];
                    acc1[2*j]   = fma2(xp, w.x, acc1[2*j]);
                    acc1[2*j+1] = fma2(xp, w.y, acc1[2*j+1]);
                }
            }
        }
#pragma unroll
        for (int j = 0; j < 30; j++) { float lo, hi; unpack2(lo, hi, acc1[j]); A[2*j] = lo; A[2*j+1] = hi; }
#pragma unroll
        for (int j = 0; j < 60; j++) A[j] = tanh_fast(A[j]);
    }

    dense2<60,30,32,true>(A, B, sW + OW2, sW + OB2);   // L2
    dense2<30,10,12,true>(B, A, sW + OW3, sW + OB3);   // L3
    float zc[4];
    dense2<10,4,4,false>(A, zc, sW + OW4, sW + OB4);   // L4 (latent)
    reinterpret_cast<float4*>(zc_out)[n] = make_float4(zc[0], zc[1], zc[2], zc[3]);

    dense2<4,10,12,true>(zc, B, sW + OW5, sW + OB5);   // L5
    dense2<10,30,32,true>(B, A, sW + OW6, sW + OB6);   // L6
    dense2<30,60,60,true>(A, B, sW + OW7, sW + OB7);   // L7
    float z9[12];
    dense2<60,10,12,true>(B, z9, sW + OW89, sW + OB89); // fused L8+L9

    // L10 + softmax
    float g[12];
    dense2<10,10,12,false>(z9, g, sW + OW10, sW + OB10);
    float m = g[0];
#pragma unroll
    for (int j = 1; j < 10; j++) m = fmaxf(m, g[j]);
    float s = 0.f;
#pragma unroll
    for (int j = 0; j < 10; j++) { g[j] = __expf(g[j] - m); s += g[j]; }
    float inv = __fdividef(1.0f, s);
    float2* gp = reinterpret_cast<float2*>(gamma_out + (size_t)n * 10);
#pragma unroll
    for (int t = 0; t < 5; t++) gp[t] = make_float2(g[2*t] * inv, g[2*t+1] * inv);
}

// ---------- phase 2: moment reduction ----------
__global__ __launch_bounds__(256)
void phase2(const float* __restrict__ gamma, const float* __restrict__ zc, int N) {
    float acc[150];
#pragma unroll
    for (int v = 0; v < 150; v++) acc[v] = 0.0f;

    int stride = gridDim.x * blockDim.x;
    for (int n = blockIdx.x * blockDim.x + threadIdx.x; n < N; n += stride) {
        float g[10];
        const float2* gp = reinterpret_cast<const float2*>(gamma + (size_t)n * 10);
#pragma unroll
        for (int t = 0; t < 5; t++) { float2 v = gp[t]; g[2*t] = v.x; g[2*t+1] = v.y; }
        float4 z4 = reinterpret_cast<const float4*>(zc)[n];
        float zv[4] = {z4.x, z4.y, z4.z, z4.w};
        float zz[10];
        {
            int t = 0;
#pragma unroll
            for (int d = 0; d < 4; d++)
#pragma unroll
                for (int e = d; e < 4; e++) zz[t++] = zv[d] * zv[e];
        }
#pragma unroll
        for (int k = 0; k < 10; k++) {
            float gk = g[k];
            acc[k] += gk;
#pragma unroll
            for (int d = 0; d < 4; d++) acc[10 + k*4 + d] += gk * zv[d];
#pragma unroll
            for (int t = 0; t < 10; t++) acc[50 + k*10 + t] += gk * zz[t];
        }
    }
#pragma unroll
    for (int v = 0; v < 150; v++) {
        float x = acc[v];
        x += __shfl_xor_sync(0xffffffffu, x, 16);
        x += __shfl_xor_sync(0xffffffffu, x, 8);
        x += __shfl_xor_sync(0xffffffffu, x, 4);
        x += __shfl_xor_sync(0xffffffffu, x, 2);
        x += __shfl_xor_sync(0xffffffffu, x, 1);
        acc[v] = x;
    }
    if ((threadIdx.x & 31) == 0) {
#pragma unroll
        for (int v = 0; v < 150; v++) atomicAdd(&g_stats[v], acc[v]);
    }
}

// ---------- phase 3: GMM params, Cholesky, precision ----------
__global__ void phase3(float* __restrict__ cov_out, float invN) {
    int k = threadIdx.x;
    if (k >= 10) return;
    float sg = g_stats[k];
    float isg = 1.0f / sg;
    float mu[4];
#pragma unroll
    for (int d = 0; d < 4; d++) mu[d] = g_stats[10 + 4*k + d] * isg;
    float C[4][4];
    {
        int t = 0;
#pragma unroll
        for (int d = 0; d < 4; d++)
#pragma unroll
            for (int e = d; e < 4; e++) {
                float c = g_stats[50 + 10*k + t] * isg - mu[d] * mu[e];
                C[d][e] = c; C[e][d] = c; t++;
            }
    }
#pragma unroll
    for (int d = 0; d < 4; d++)
#pragma unroll
        for (int e = 0; e < 4; e++) cov_out[k*16 + d*4 + e] = C[d][e];

#pragma unroll
    for (int d = 0; d < 4; d++) C[d][d] += 1e-6f;

    float L00 = sqrtf(C[0][0]);
    float L10 = C[1][0] / L00, L20 = C[2][0] / L00, L30 = C[3][0] / L00;
    float L11 = sqrtf(C[1][1] - L10*L10);
    float L21 = (C[2][1] - L20*L10) / L11;
    float L31 = (C[3][1] - L30*L10) / L11;
    float L22 = sqrtf(C[2][2] - L20*L20 - L21*L21);
    float L32 = (C[3][2] - L30*L20 - L31*L21) / L22;
    float L33 = sqrtf(C[3][3] - L30*L30 - L31*L31 - L32*L32);
    float logdet = 2.0f * (logf(L00) + logf(L11) + logf(L22) + logf(L33));

    float M00 = 1.0f/L00, M11 = 1.0f/L11, M22 = 1.0f/L22, M33 = 1.0f/L33;
    float M10 = -L10 * M00 * M11;
    float M20 = -(L20*M00 + L21*M10) * M22;
    float M21 = -L21 * M11 * M22;
    float M30 = -(L30*M00 + L31*M10 + L32*M20) * M33;
    float M31 = -(L31*M11 + L32*M21) * M33;
    float M32 = -L32 * M22 * M33;

    float P[4][4];
    P[0][0] = M00*M00 + M10*M10 + M20*M20 + M30*M30;
    P[0][1] = M10*M11 + M20*M21 + M30*M31;
    P[0][2] = M20*M22 + M30*M32;
    P[0][3] = M30*M33;
    P[1][1] = M11*M11 + M21*M21 + M31*M31;
    P[1][2] = M21*M22 + M31*M32;
    P[1][3] = M31*M33;
    P[2][2] = M22*M22 + M32*M32;
    P[2][3] = M32*M33;
    P[3][3] = M33*M33;
    P[1][0] = P[0][1]; P[2][0] = P[0][2]; P[3][0] = P[0][3];
    P[2][1] = P[1][2]; P[3][1] = P[1][3]; P[3][2] = P[2][3];

    float phi = sg * invN;
    const float LOG2PI = 1.8378770664093453f;
    float ck = logf(phi) - 0.5f * (logdet + 4.0f * LOG2PI);

    float* o = g_gmm + k * 21;
#pragma unroll
    for (int d = 0; d < 4; d++) o[d] = mu[d];
#pragma unroll
    for (int d = 0; d < 4; d++)
#pragma unroll
        for (int e = 0; e < 4; e++) o[4 + d*4 + e] = P[d][e];
    o[20] = ck;
}

// ---------- phase 4: per-sample energy ----------
__global__ __launch_bounds__(256)
void phase4(const float* __restrict__ zc, float* __restrict__ energy, int N) {
    __shared__ float sp[212];
    if (threadIdx.x < 212) sp[threadIdx.x] = g_gmm[threadIdx.x];
    __syncthreads();
    int n = blockIdx.x * blockDim.x + threadIdx.x;
    if (n >= N) return;
    float4 z = reinterpret_cast<const float4*>(zc)[n];
    float lp[10];
    float m = -1e30f;
#pragma unroll
    for (int k = 0; k < 10; k++) {
        const float* o = sp + k * 21;
        float d0 = z.x - o[0], d1 = z.y - o[1], d2 = z.z - o[2], d3 = z.w - o[3];
        const float* P = o + 4;
        float q = d0 * (P[0]*d0  + P[1]*d1  + P[2]*d2  + P[3]*d3)
                + d1 * (P[4]*d0  + P[5]*d1  + P[6]*d2  + P[7]*d3)
                + d2 * (P[8]*d0  + P[9]*d1  + P[10]*d2 + P[11]*d3)
                + d3 * (P[12]*d0 + P[13]*d1 + P[14]*d2 + P[15]*d3);
        lp[k] = o[20] - 0.5f * q;
        m = fmaxf(m, lp[k]);
    }
    float s = 0.f;
#pragma unroll
    for (int k = 0; k < 10; k++) s += __expf(lp[k] - m);
    energy[n] = -(m + __logf(s));
}

// ---------- launcher ----------
extern "C" void kernel_launch(void* const* d_in, const int* in_sizes, int n_in,
                              void* d_out, int out_size) {
    const float* x = (const float*)d_in[0];
    Params p;
    for (int i = 0; i < 10; i++) {
        p.w[i] = (const float*)d_in[1 + 2*i];
        p.b[i] = (const float*)d_in[2 + 2*i];
    }
    int N = in_sizes[0] / 120;

    float* out    = (float*)d_out;
    float* energy = out;                       // [N]
    float* gamma  = out + N;                   // [N,10]
    float* zcbuf  = out + (size_t)11 * N;      // [N,4]
    float* covbuf = out + (size_t)15 * N;      // [10,4,4]

    cudaFuncSetAttribute(phase1, cudaFuncAttributeMaxDynamicSharedMemorySize, SMEM_BYTES);

    prep<<<1, 256>>>(p);
    phase1<<<(N + TPB - 1) / TPB, TPB, SMEM_BYTES>>>(x, gamma, zcbuf, N);
    phase2<<<296, 256>>>(gamma, zcbuf, N);
    phase3<<<1, 32>>>(covbuf, 1.0f / (float)N);
    phase4<<<(N + 255) / 256, 256>>>(zcbuf, energy, N);
}